// round 4
// baseline (speedup 1.0000x reference)
#include <cuda_runtime.h>
#include <cstdint>

#define BATCH 16
#define T 1024
#define D 256
#define BM 128      // CTA tile m
#define BN 256      // CTA tile n
#define BK 32
#define NCH (D / BK)   // 8 chunks
#define PAD 36         // padded row stride (floats): conflict-free frags, 144B rows (16B aligned)

// Scratch (allocation-free rule: __device__ globals)
__device__ float g_xs[(size_t)BATCH * T * D];   // tf32-rounded x * w3
__device__ float g_yt[(size_t)BATCH * T * D];   // tf32-rounded y
__device__ float g_bias_x[BATCH * T];
__device__ float g_bias_y[BATCH * T];

__device__ __forceinline__ float to_tf32f(float f) {
    uint32_t r;
    asm("cvt.rna.tf32.f32 %0, %1;" : "=r"(r) : "f"(f));
    return __uint_as_float(r);
}

__device__ __forceinline__ uint32_t smem_u32(const void* p) {
    uint32_t a;
    asm("{ .reg .u64 t; cvta.to.shared.u64 t, %1; cvt.u32.u64 %0, t; }" : "=r"(a) : "l"(p));
    return a;
}
__device__ __forceinline__ void cp_async16(uint32_t dst, const void* src) {
    asm volatile("cp.async.ca.shared.global [%0], [%1], 16;" :: "r"(dst), "l"(src));
}
#define CP_COMMIT() asm volatile("cp.async.commit_group;" ::: "memory")
#define CP_WAIT0()  asm volatile("cp.async.wait_group 0;" ::: "memory")

__device__ __forceinline__ void mma_tf32(float (&d)[4], const uint32_t (&a)[4],
                                         const uint32_t (&b)[2]) {
    asm volatile(
        "mma.sync.aligned.m16n8k8.row.col.f32.tf32.tf32.f32 "
        "{%0,%1,%2,%3}, {%4,%5,%6,%7}, {%8,%9}, {%0,%1,%2,%3};"
        : "+f"(d[0]), "+f"(d[1]), "+f"(d[2]), "+f"(d[3])
        : "r"(a[0]), "r"(a[1]), "r"(a[2]), "r"(a[3]), "r"(b[0]), "r"(b[1]));
}

// ---------------- prep: xs = tf32(x*w3), yt = tf32(y), bias dots in fp32 ----------------
__global__ void __launch_bounds__(256) prep_kernel(
    const float* __restrict__ x, const float* __restrict__ y, const float* __restrict__ WS) {
    int warp = blockIdx.x * 8 + (threadIdx.x >> 5);
    int lane = threadIdx.x & 31;
    const int nrows = BATCH * T;
    if (warp < nrows) {
        const float4* p4 = (const float4*)(x + (size_t)warp * D);
        const float4* w1 = (const float4*)WS;
        const float4* w3 = (const float4*)(WS + 2 * D);
        float4* xs4 = (float4*)(g_xs + (size_t)warp * D);
        float s = 0.f;
#pragma unroll
        for (int i = 0; i < 2; i++) {
            int idx = lane + i * 32;
            float4 v = p4[idx], a = w1[idx], c = w3[idx];
            s += v.x * a.x + v.y * a.y + v.z * a.z + v.w * a.w;
            xs4[idx] = make_float4(to_tf32f(v.x * c.x), to_tf32f(v.y * c.y),
                                   to_tf32f(v.z * c.z), to_tf32f(v.w * c.w));
        }
#pragma unroll
        for (int o = 16; o; o >>= 1) s += __shfl_xor_sync(0xffffffffu, s, o);
        if (lane == 0) g_bias_x[warp] = s;
    } else {
        int row = warp - nrows;
        const float4* p4 = (const float4*)(y + (size_t)row * D);
        const float4* w2 = (const float4*)(WS + D);
        float4* yt4 = (float4*)(g_yt + (size_t)row * D);
        float s = 0.f;
#pragma unroll
        for (int i = 0; i < 2; i++) {
            int idx = lane + i * 32;
            float4 v = p4[idx], a = w2[idx];
            s += v.x * a.x + v.y * a.y + v.z * a.z + v.w * a.w;
            yt4[idx] = make_float4(to_tf32f(v.x), to_tf32f(v.y),
                                   to_tf32f(v.z), to_tf32f(v.w));
        }
#pragma unroll
        for (int o = 16; o; o >>= 1) s += __shfl_xor_sync(0xffffffffu, s, o);
        if (lane == 0) g_bias_y[row] = s;
    }
}

// ---------------- tf32 warp-MMA GEMM, CTA 128x256, 8 warps of 64x64 ----------------
#define A_WORDS (BM * PAD)            // 4608
#define B_WORDS (BN * PAD)            // 9216
#define SMEM_WORDS (2 * A_WORDS + 2 * B_WORDS)
#define SMEM_BYTES (SMEM_WORDS * 4)   // 110592

__global__ void __launch_bounds__(256) gemm_mma_kernel(float* __restrict__ out) {
    extern __shared__ float sm[];
    const uint32_t sbase = smem_u32(sm);

    const int tid = threadIdx.x;
    const int wid = tid >> 5, lane = tid & 31;
    const int b = blockIdx.z;
    const int tile_m = blockIdx.y * BM;
    const int tile_n = blockIdx.x * BN;

    const float* A  = g_xs + ((size_t)b * T + tile_m) * D;
    const float* Bg = g_yt + ((size_t)b * T + tile_n) * D;

    // Warp layout: 2 (m) x 4 (n); warp tile 64 x 64
    const int warp_m = (wid >> 2) * 64;
    const int warp_n = (wid & 3) * 64;
    const int gid = lane >> 2;     // 0..7
    const int ctg = lane & 3;      // 0..3

    float acc[4][8][4];
#pragma unroll
    for (int i = 0; i < 4; i++)
#pragma unroll
        for (int j = 0; j < 8; j++)
#pragma unroll
            for (int r = 0; r < 4; r++) acc[i][j][r] = 0.f;

    // cp.async staging: A 128 rows x 8 q-slots (4 tasks/thread), B 256 x 8 (8 tasks/thread)
    const int st_row = tid >> 3;   // base row (task mapping: task = tid + 256*i)
    const int st_q   = tid & 7;

    auto load_chunk = [&](int chunk, int buf) {
        const float* ap = A  + chunk * BK + st_q * 4;
        const float* bp = Bg + chunk * BK + st_q * 4;
        uint32_t adst = sbase + (buf * A_WORDS + st_row * PAD + st_q * 4) * 4;
        uint32_t bdst = sbase + ((2 * A_WORDS) + buf * B_WORDS + st_row * PAD + st_q * 4) * 4;
#pragma unroll
        for (int i = 0; i < 4; i++)
            cp_async16(adst + i * 32 * PAD * 4, ap + (size_t)(st_row + 32 * i) * D);
#pragma unroll
        for (int i = 0; i < 8; i++)
            cp_async16(bdst + i * 32 * PAD * 4, bp + (size_t)(st_row + 32 * i) * D);
    };

    load_chunk(0, 0);
    CP_COMMIT();
    CP_WAIT0();
    __syncthreads();

#pragma unroll 1
    for (int c = 0; c < NCH; c++) {
        if (c + 1 < NCH) {
            load_chunk(c + 1, (c + 1) & 1);
            CP_COMMIT();
        }

        const uint32_t* ab = (const uint32_t*)sm + (c & 1) * A_WORDS + warp_m * PAD;
        const uint32_t* bb = (const uint32_t*)sm + 2 * A_WORDS + (c & 1) * B_WORDS + warp_n * PAD;
#pragma unroll
        for (int ks = 0; ks < 4; ks++) {
            const int k0 = ks * 8 + ctg;
            uint32_t af[4][4], bf[8][2];
#pragma unroll
            for (int mf = 0; mf < 4; mf++) {
                int m = mf * 16 + gid;
                af[mf][0] = ab[m * PAD + k0];
                af[mf][1] = ab[(m + 8) * PAD + k0];
                af[mf][2] = ab[m * PAD + k0 + 4];
                af[mf][3] = ab[(m + 8) * PAD + k0 + 4];
            }
#pragma unroll
            for (int nf = 0; nf < 8; nf++) {
                int n = nf * 8 + gid;
                bf[nf][0] = bb[n * PAD + k0];
                bf[nf][1] = bb[n * PAD + k0 + 4];
            }
#pragma unroll
            for (int mf = 0; mf < 4; mf++)
#pragma unroll
                for (int nf = 0; nf < 8; nf++) mma_tf32(acc[mf][nf], af[mf], bf[nf]);
        }

        if (c + 1 < NCH) {
            CP_WAIT0();
            __syncthreads();
        }
    }

    // Epilogue: + bias_x[row] + bias_y[col], float2 stores
    const float* bxp = g_bias_x + b * T + tile_m + warp_m;
    const float* byp = g_bias_y + b * T + tile_n + warp_n;
    float2 by[8];
#pragma unroll
    for (int nf = 0; nf < 8; nf++)
        by[nf] = *(const float2*)(byp + nf * 8 + ctg * 2);

#pragma unroll
    for (int mf = 0; mf < 4; mf++) {
        int r0 = warp_m + mf * 16 + gid;
        float bx0 = bxp[mf * 16 + gid];
        float bx1 = bxp[mf * 16 + gid + 8];
        float* C0 = out + ((size_t)b * T + tile_m + r0) * T + tile_n + warp_n;
        float* C1 = C0 + 8 * T;
#pragma unroll
        for (int nf = 0; nf < 8; nf++) {
            int coff = nf * 8 + ctg * 2;
            float2 v0 = make_float2(acc[mf][nf][0] + bx0 + by[nf].x,
                                    acc[mf][nf][1] + bx0 + by[nf].y);
            float2 v1 = make_float2(acc[mf][nf][2] + bx1 + by[nf].x,
                                    acc[mf][nf][3] + bx1 + by[nf].y);
            *(float2*)(C0 + coff) = v0;
            *(float2*)(C1 + coff) = v1;
        }
    }
}

extern "C" void kernel_launch(void* const* d_in, const int* in_sizes, int n_in,
                              void* d_out, int out_size) {
    const float* x  = (const float*)d_in[0];
    const float* y  = (const float*)d_in[1];
    const float* WS = (const float*)d_in[2];
    float* out = (float*)d_out;

    cudaFuncSetAttribute(gemm_mma_kernel, cudaFuncAttributeMaxDynamicSharedMemorySize, SMEM_BYTES);

    prep_kernel<<<(2 * BATCH * T) / 8, 256>>>(x, y, WS);

    dim3 grid(T / BN, T / BM, BATCH);   // (4, 8, 16) = 512 CTAs
    gemm_mma_kernel<<<grid, 256, SMEM_BYTES>>>(out);
}

// round 5
// speedup vs baseline: 1.0571x; 1.0571x over previous
#include <cuda_runtime.h>
#include <cstdint>

#define BATCH 16
#define T 1024
#define D 256
#define BM 128
#define BN 128
#define BK 32
#define NCH (D / BK)   // 8 chunks
#define PAD 36         // padded row stride (floats): conflict-free frags, 144B rows

// Scratch (allocation-free rule: __device__ globals)
__device__ float g_xs[(size_t)BATCH * T * D];   // tf32-rounded x * w3
__device__ float g_yt[(size_t)BATCH * T * D];   // tf32-rounded y
__device__ float g_bias_x[BATCH * T];
__device__ float g_bias_y[BATCH * T];

__device__ __forceinline__ float to_tf32f(float f) {
    uint32_t r;
    asm("cvt.rna.tf32.f32 %0, %1;" : "=r"(r) : "f"(f));
    return __uint_as_float(r);
}
__device__ __forceinline__ uint32_t smem_u32(const void* p) {
    uint32_t a;
    asm("{ .reg .u64 t; cvta.to.shared.u64 t, %1; cvt.u32.u64 %0, t; }" : "=r"(a) : "l"(p));
    return a;
}
__device__ __forceinline__ void cp_async16(uint32_t dst, const void* src) {
    asm volatile("cp.async.ca.shared.global [%0], [%1], 16;" :: "r"(dst), "l"(src));
}
#define CP_COMMIT() asm volatile("cp.async.commit_group;" ::: "memory")
#define CP_WAIT0()  asm volatile("cp.async.wait_group 0;" ::: "memory")

__device__ __forceinline__ void mma_tf32(float (&d)[4], const uint32_t (&a)[4],
                                         const uint32_t (&b)[2]) {
    asm volatile(
        "mma.sync.aligned.m16n8k8.row.col.f32.tf32.tf32.f32 "
        "{%0,%1,%2,%3}, {%4,%5,%6,%7}, {%8,%9}, {%0,%1,%2,%3};"
        : "+f"(d[0]), "+f"(d[1]), "+f"(d[2]), "+f"(d[3])
        : "r"(a[0]), "r"(a[1]), "r"(a[2]), "r"(a[3]), "r"(b[0]), "r"(b[1]));
}

// ---------------- prep: xs = tf32(x*w3), yt = tf32(y), bias dots in fp32 ----------------
__global__ void __launch_bounds__(256) prep_kernel(
    const float* __restrict__ x, const float* __restrict__ y, const float* __restrict__ WS) {
    int warp = blockIdx.x * 8 + (threadIdx.x >> 5);
    int lane = threadIdx.x & 31;
    const int nrows = BATCH * T;
    if (warp < nrows) {
        const float4* p4 = (const float4*)(x + (size_t)warp * D);
        const float4* w1 = (const float4*)WS;
        const float4* w3 = (const float4*)(WS + 2 * D);
        float4* xs4 = (float4*)(g_xs + (size_t)warp * D);
        float s = 0.f;
#pragma unroll
        for (int i = 0; i < 2; i++) {
            int idx = lane + i * 32;
            float4 v = p4[idx], a = w1[idx], c = w3[idx];
            s += v.x * a.x + v.y * a.y + v.z * a.z + v.w * a.w;
            xs4[idx] = make_float4(to_tf32f(v.x * c.x), to_tf32f(v.y * c.y),
                                   to_tf32f(v.z * c.z), to_tf32f(v.w * c.w));
        }
#pragma unroll
        for (int o = 16; o; o >>= 1) s += __shfl_xor_sync(0xffffffffu, s, o);
        if (lane == 0) g_bias_x[warp] = s;
    } else {
        int row = warp - nrows;
        const float4* p4 = (const float4*)(y + (size_t)row * D);
        const float4* w2 = (const float4*)(WS + D);
        float4* yt4 = (float4*)(g_yt + (size_t)row * D);
        float s = 0.f;
#pragma unroll
        for (int i = 0; i < 2; i++) {
            int idx = lane + i * 32;
            float4 v = p4[idx], a = w2[idx];
            s += v.x * a.x + v.y * a.y + v.z * a.z + v.w * a.w;
            yt4[idx] = make_float4(to_tf32f(v.x), to_tf32f(v.y),
                                   to_tf32f(v.z), to_tf32f(v.w));
        }
#pragma unroll
        for (int o = 16; o; o >>= 1) s += __shfl_xor_sync(0xffffffffu, s, o);
        if (lane == 0) g_bias_y[row] = s;
    }
}

// ---------------- tf32 warp-MMA GEMM: CTA 128x128, 128 threads, 4 warps of 64x64 ----------------
#define A_WORDS (BM * PAD)            // 4608
#define B_WORDS (BN * PAD)            // 4608
#define SMEM_WORDS (2 * A_WORDS + 2 * B_WORDS)
#define SMEM_BYTES (SMEM_WORDS * 4)   // 73728 -> 3 CTAs/SM

__global__ void __launch_bounds__(128, 3) gemm_mma_kernel(float* __restrict__ out) {
    extern __shared__ float sm[];
    const uint32_t sbase = smem_u32(sm);

    const int tid = threadIdx.x;
    const int wid = tid >> 5, lane = tid & 31;
    const int b = blockIdx.z;
    const int tile_m = blockIdx.y * BM;
    const int tile_n = blockIdx.x * BN;

    const float* A  = g_xs + ((size_t)b * T + tile_m) * D;
    const float* Bg = g_yt + ((size_t)b * T + tile_n) * D;

    // Warp layout: 2 (m) x 2 (n); warp tile 64 x 64
    const int warp_m = (wid >> 1) * 64;
    const int warp_n = (wid & 1) * 64;
    const int gid = lane >> 2;     // 0..7
    const int ctg = lane & 3;      // 0..3

    float acc[4][8][4];
#pragma unroll
    for (int i = 0; i < 4; i++)
#pragma unroll
        for (int j = 0; j < 8; j++)
#pragma unroll
            for (int r = 0; r < 4; r++) acc[i][j][r] = 0.f;

    // cp.async staging: 128 threads cover (128 rows x 8 q) per operand -> 8 tasks each
    const int st_row = tid >> 3;   // 0..15
    const int st_q   = tid & 7;

    auto load_chunk = [&](int chunk, int buf) {
        const float* ap = A  + chunk * BK + st_q * 4;
        const float* bp = Bg + chunk * BK + st_q * 4;
        uint32_t adst = sbase + (buf * A_WORDS + st_row * PAD + st_q * 4) * 4;
        uint32_t bdst = sbase + ((2 * A_WORDS) + buf * B_WORDS + st_row * PAD + st_q * 4) * 4;
#pragma unroll
        for (int i = 0; i < 8; i++)
            cp_async16(adst + i * 16 * PAD * 4, ap + (size_t)(st_row + 16 * i) * D);
#pragma unroll
        for (int i = 0; i < 8; i++)
            cp_async16(bdst + i * 16 * PAD * 4, bp + (size_t)(st_row + 16 * i) * D);
    };

    load_chunk(0, 0);
    CP_COMMIT();
    CP_WAIT0();
    __syncthreads();

#pragma unroll 1
    for (int c = 0; c < NCH; c++) {
        if (c + 1 < NCH) {
            load_chunk(c + 1, (c + 1) & 1);
            CP_COMMIT();
        }

        const uint32_t* ab = (const uint32_t*)sm + (c & 1) * A_WORDS + warp_m * PAD;
        const uint32_t* bb = (const uint32_t*)sm + 2 * A_WORDS + (c & 1) * B_WORDS + warp_n * PAD;
#pragma unroll
        for (int ks = 0; ks < 4; ks++) {
            const int k0 = ks * 8 + ctg;
            uint32_t af[4][4], bf[8][2];
#pragma unroll
            for (int mf = 0; mf < 4; mf++) {
                int m = mf * 16 + gid;
                af[mf][0] = ab[m * PAD + k0];
                af[mf][1] = ab[(m + 8) * PAD + k0];
                af[mf][2] = ab[m * PAD + k0 + 4];
                af[mf][3] = ab[(m + 8) * PAD + k0 + 4];
            }
#pragma unroll
            for (int nf = 0; nf < 8; nf++) {
                int n = nf * 8 + gid;
                bf[nf][0] = bb[n * PAD + k0];
                bf[nf][1] = bb[n * PAD + k0 + 4];
            }
#pragma unroll
            for (int mf = 0; mf < 4; mf++)
#pragma unroll
                for (int nf = 0; nf < 8; nf++) mma_tf32(acc[mf][nf], af[mf], bf[nf]);
        }

        if (c + 1 < NCH) {
            CP_WAIT0();
            __syncthreads();
        }
    }

    // Epilogue: + bias_x[row] + bias_y[col], float2 stores
    const float* bxp = g_bias_x + b * T + tile_m + warp_m;
    const float* byp = g_bias_y + b * T + tile_n + warp_n;
    float2 by[8];
#pragma unroll
    for (int nf = 0; nf < 8; nf++)
        by[nf] = *(const float2*)(byp + nf * 8 + ctg * 2);

#pragma unroll
    for (int mf = 0; mf < 4; mf++) {
        int r0 = warp_m + mf * 16 + gid;
        float bx0 = bxp[mf * 16 + gid];
        float bx1 = bxp[mf * 16 + gid + 8];
        float* C0 = out + ((size_t)b * T + tile_m + r0) * T + tile_n + warp_n;
        float* C1 = C0 + 8 * T;
#pragma unroll
        for (int nf = 0; nf < 8; nf++) {
            int coff = nf * 8 + ctg * 2;
            float2 v0 = make_float2(acc[mf][nf][0] + bx0 + by[nf].x,
                                    acc[mf][nf][1] + bx0 + by[nf].y);
            float2 v1 = make_float2(acc[mf][nf][2] + bx1 + by[nf].x,
                                    acc[mf][nf][3] + bx1 + by[nf].y);
            *(float2*)(C0 + coff) = v0;
            *(float2*)(C1 + coff) = v1;
        }
    }
}

extern "C" void kernel_launch(void* const* d_in, const int* in_sizes, int n_in,
                              void* d_out, int out_size) {
    const float* x  = (const float*)d_in[0];
    const float* y  = (const float*)d_in[1];
    const float* WS = (const float*)d_in[2];
    float* out = (float*)d_out;

    cudaFuncSetAttribute(gemm_mma_kernel, cudaFuncAttributeMaxDynamicSharedMemorySize, SMEM_BYTES);

    prep_kernel<<<(2 * BATCH * T) / 8, 256>>>(x, y, WS);

    dim3 grid(T / BN, T / BM, BATCH);   // (8, 8, 16) = 1024 CTAs
    gemm_mma_kernel<<<grid, 128, SMEM_BYTES>>>(out);
}

// round 6
// speedup vs baseline: 1.6054x; 1.5186x over previous
#include <cuda_runtime.h>
#include <cuda_fp16.h>
#include <cstdint>

#define BATCH 16
#define T 1024
#define D 256
#define BM 128
#define BN 128
#define BK 64
#define NCH (D / BK)   // 4 chunks
#define PADH 72        // halfs per row (64 + 8 pad) = 144 B rows; conflict-free frags

// Scratch (allocation-free rule: __device__ globals)
__device__ __half g_xs[(size_t)BATCH * T * D];  // fp16(x * w3)
__device__ __half g_yt[(size_t)BATCH * T * D];  // fp16(y)
__device__ float g_bias_x[BATCH * T];
__device__ float g_bias_y[BATCH * T];

__device__ __forceinline__ uint32_t smem_u32(const void* p) {
    uint32_t a;
    asm("{ .reg .u64 t; cvta.to.shared.u64 t, %1; cvt.u32.u64 %0, t; }" : "=r"(a) : "l"(p));
    return a;
}
__device__ __forceinline__ void cp_async16(uint32_t dst, const void* src) {
    asm volatile("cp.async.ca.shared.global [%0], [%1], 16;" :: "r"(dst), "l"(src));
}
#define CP_COMMIT() asm volatile("cp.async.commit_group;" ::: "memory")
#define CP_WAIT0()  asm volatile("cp.async.wait_group 0;" ::: "memory")

// fp16 MMA, f32 accumulate: m16n8k16
__device__ __forceinline__ void mma_f16(float (&d)[4], const uint32_t (&a)[4],
                                        const uint32_t (&b)[2]) {
    asm volatile(
        "mma.sync.aligned.m16n8k16.row.col.f32.f16.f16.f32 "
        "{%0,%1,%2,%3}, {%4,%5,%6,%7}, {%8,%9}, {%0,%1,%2,%3};"
        : "+f"(d[0]), "+f"(d[1]), "+f"(d[2]), "+f"(d[3])
        : "r"(a[0]), "r"(a[1]), "r"(a[2]), "r"(a[3]), "r"(b[0]), "r"(b[1]));
}

// ---------------- prep: xs = fp16(x*w3), yt = fp16(y), bias dots in fp32 ----------------
__global__ void __launch_bounds__(256) prep_kernel(
    const float* __restrict__ x, const float* __restrict__ y, const float* __restrict__ WS) {
    int warp = blockIdx.x * 8 + (threadIdx.x >> 5);
    int lane = threadIdx.x & 31;
    const int nrows = BATCH * T;
    if (warp < nrows) {
        const float4* p4 = (const float4*)(x + (size_t)warp * D);
        const float4* w1 = (const float4*)WS;
        const float4* w3 = (const float4*)(WS + 2 * D);
        __half2* xs2 = (__half2*)(g_xs + (size_t)warp * D);
        float s = 0.f;
#pragma unroll
        for (int i = 0; i < 2; i++) {
            int idx = lane + i * 32;
            float4 v = p4[idx], a = w1[idx], c = w3[idx];
            s += v.x * a.x + v.y * a.y + v.z * a.z + v.w * a.w;
            xs2[idx * 2 + 0] = __floats2half2_rn(v.x * c.x, v.y * c.y);
            xs2[idx * 2 + 1] = __floats2half2_rn(v.z * c.z, v.w * c.w);
        }
#pragma unroll
        for (int o = 16; o; o >>= 1) s += __shfl_xor_sync(0xffffffffu, s, o);
        if (lane == 0) g_bias_x[warp] = s;
    } else {
        int row = warp - nrows;
        const float4* p4 = (const float4*)(y + (size_t)row * D);
        const float4* w2 = (const float4*)(WS + D);
        __half2* yt2 = (__half2*)(g_yt + (size_t)row * D);
        float s = 0.f;
#pragma unroll
        for (int i = 0; i < 2; i++) {
            int idx = lane + i * 32;
            float4 v = p4[idx], a = w2[idx];
            s += v.x * a.x + v.y * a.y + v.z * a.z + v.w * a.w;
            yt2[idx * 2 + 0] = __floats2half2_rn(v.x, v.y);
            yt2[idx * 2 + 1] = __floats2half2_rn(v.z, v.w);
        }
#pragma unroll
        for (int o = 16; o; o >>= 1) s += __shfl_xor_sync(0xffffffffu, s, o);
        if (lane == 0) g_bias_y[row] = s;
    }
}

// ---------------- fp16 warp-MMA GEMM: CTA 128x128, 128 threads, 4 warps of 64x64 ----------------
#define A_BYTES (BM * PADH * 2)        // 18432
#define B_BYTES (BN * PADH * 2)        // 18432
#define SMEM_BYTES (2 * A_BYTES + 2 * B_BYTES)   // 73728 -> 3 CTAs/SM

__global__ void __launch_bounds__(128, 3) gemm_mma_kernel(float* __restrict__ out) {
    extern __shared__ char smc[];
    const uint32_t sbase = smem_u32(smc);

    const int tid = threadIdx.x;
    const int wid = tid >> 5, lane = tid & 31;
    const int b = blockIdx.z;
    const int tile_m = blockIdx.y * BM;
    const int tile_n = blockIdx.x * BN;

    const __half* A  = g_xs + ((size_t)b * T + tile_m) * D;
    const __half* Bg = g_yt + ((size_t)b * T + tile_n) * D;

    // Warp layout: 2 (m) x 2 (n); warp tile 64 x 64
    const int warp_m = (wid >> 1) * 64;
    const int warp_n = (wid & 1) * 64;
    const int gid = lane >> 2;     // 0..7
    const int ctg = lane & 3;      // 0..3

    float acc[4][8][4];
#pragma unroll
    for (int i = 0; i < 4; i++)
#pragma unroll
        for (int j = 0; j < 8; j++)
#pragma unroll
            for (int r = 0; r < 4; r++) acc[i][j][r] = 0.f;

    // cp.async staging: per chunk per operand 128 rows x 8 16B-slots = 1024 tasks; 8 per thread
    const int st_row = tid >> 3;   // 0..15
    const int st_q   = tid & 7;    // 16B slot (8 halfs)

    auto load_chunk = [&](int chunk, int buf) {
        const __half* ap = A  + chunk * BK + st_q * 8;
        const __half* bp = Bg + chunk * BK + st_q * 8;
        uint32_t adst = sbase + buf * A_BYTES + st_row * (PADH * 2) + st_q * 16;
        uint32_t bdst = sbase + 2 * A_BYTES + buf * B_BYTES + st_row * (PADH * 2) + st_q * 16;
#pragma unroll
        for (int i = 0; i < 8; i++)
            cp_async16(adst + i * 16 * PADH * 2, ap + (size_t)(st_row + 16 * i) * D);
#pragma unroll
        for (int i = 0; i < 8; i++)
            cp_async16(bdst + i * 16 * PADH * 2, bp + (size_t)(st_row + 16 * i) * D);
    };

    load_chunk(0, 0);
    CP_COMMIT();
    CP_WAIT0();
    __syncthreads();

    const int PW = PADH / 2;  // 36 words per row

#pragma unroll 1
    for (int c = 0; c < NCH; c++) {
        if (c + 1 < NCH) {
            load_chunk(c + 1, (c + 1) & 1);
            CP_COMMIT();
        }

        const uint32_t* ab = (const uint32_t*)(smc + (c & 1) * A_BYTES) + warp_m * PW;
        const uint32_t* bb = (const uint32_t*)(smc + 2 * A_BYTES + (c & 1) * B_BYTES) + warp_n * PW;
#pragma unroll
        for (int ks = 0; ks < 4; ks++) {          // 4 k16 steps per 64-chunk
            const int k0 = ks * 8 + ctg;          // word offset: k16 = 8 words
            uint32_t af[4][4], bf[8][2];
#pragma unroll
            for (int mf = 0; mf < 4; mf++) {
                int m = mf * 16 + gid;
                af[mf][0] = ab[m * PW + k0];
                af[mf][1] = ab[(m + 8) * PW + k0];
                af[mf][2] = ab[m * PW + k0 + 4];
                af[mf][3] = ab[(m + 8) * PW + k0 + 4];
            }
#pragma unroll
            for (int nf = 0; nf < 8; nf++) {
                int n = nf * 8 + gid;
                bf[nf][0] = bb[n * PW + k0];
                bf[nf][1] = bb[n * PW + k0 + 4];
            }
#pragma unroll
            for (int mf = 0; mf < 4; mf++)
#pragma unroll
                for (int nf = 0; nf < 8; nf++) mma_f16(acc[mf][nf], af[mf], bf[nf]);
        }

        if (c + 1 < NCH) {
            CP_WAIT0();
            __syncthreads();
        }
    }

    // Epilogue: + bias_x[row] + bias_y[col], float2 stores
    const float* bxp = g_bias_x + b * T + tile_m + warp_m;
    const float* byp = g_bias_y + b * T + tile_n + warp_n;
    float2 by[8];
#pragma unroll
    for (int nf = 0; nf < 8; nf++)
        by[nf] = *(const float2*)(byp + nf * 8 + ctg * 2);

#pragma unroll
    for (int mf = 0; mf < 4; mf++) {
        int r0 = warp_m + mf * 16 + gid;
        float bx0 = bxp[mf * 16 + gid];
        float bx1 = bxp[mf * 16 + gid + 8];
        float* C0 = out + ((size_t)b * T + tile_m + r0) * T + tile_n + warp_n;
        float* C1 = C0 + 8 * T;
#pragma unroll
        for (int nf = 0; nf < 8; nf++) {
            int coff = nf * 8 + ctg * 2;
            float2 v0 = make_float2(acc[mf][nf][0] + bx0 + by[nf].x,
                                    acc[mf][nf][1] + bx0 + by[nf].y);
            float2 v1 = make_float2(acc[mf][nf][2] + bx1 + by[nf].x,
                                    acc[mf][nf][3] + bx1 + by[nf].y);
            *(float2*)(C0 + coff) = v0;
            *(float2*)(C1 + coff) = v1;
        }
    }
}

extern "C" void kernel_launch(void* const* d_in, const int* in_sizes, int n_in,
                              void* d_out, int out_size) {
    const float* x  = (const float*)d_in[0];
    const float* y  = (const float*)d_in[1];
    const float* WS = (const float*)d_in[2];
    float* out = (float*)d_out;

    cudaFuncSetAttribute(gemm_mma_kernel, cudaFuncAttributeMaxDynamicSharedMemorySize, SMEM_BYTES);

    prep_kernel<<<(2 * BATCH * T) / 8, 256>>>(x, y, WS);

    dim3 grid(T / BN, T / BM, BATCH);   // (8, 8, 16) = 1024 CTAs
    gemm_mma_kernel<<<grid, 128, SMEM_BYTES>>>(out);
}

// round 7
// speedup vs baseline: 1.6799x; 1.0464x over previous
#include <cuda_runtime.h>
#include <cuda_fp16.h>
#include <cstdint>

#define BATCH 16
#define T 1024
#define D 256
#define BM 128
#define BN 128
#define BK 64
#define NCH (D / BK)   // 4 chunks
#define PADH 72        // halfs per row (64 + 8 pad) = 144 B rows; conflict-free ldmatrix
#define ROWB (PADH * 2)

// Scratch (allocation-free rule: __device__ globals)
__device__ __half g_xs[(size_t)BATCH * T * D];  // fp16(x * w3)
__device__ __half g_yt[(size_t)BATCH * T * D];  // fp16(y)
__device__ float g_bias_x[BATCH * T];
__device__ float g_bias_y[BATCH * T];

__device__ __forceinline__ uint32_t smem_u32(const void* p) {
    uint32_t a;
    asm("{ .reg .u64 t; cvta.to.shared.u64 t, %1; cvt.u32.u64 %0, t; }" : "=r"(a) : "l"(p));
    return a;
}
__device__ __forceinline__ void cp_async16(uint32_t dst, const void* src) {
    asm volatile("cp.async.ca.shared.global [%0], [%1], 16;" :: "r"(dst), "l"(src));
}
#define CP_COMMIT() asm volatile("cp.async.commit_group;" ::: "memory")
#define CP_WAIT0()  asm volatile("cp.async.wait_group 0;" ::: "memory")

__device__ __forceinline__ void ldsm_x4(uint32_t (&r)[4], uint32_t addr) {
    asm volatile("ldmatrix.sync.aligned.m8n8.x4.shared.b16 {%0,%1,%2,%3}, [%4];"
        : "=r"(r[0]), "=r"(r[1]), "=r"(r[2]), "=r"(r[3]) : "r"(addr));
}

__device__ __forceinline__ void mma_f16(float (&d)[4], const uint32_t (&a)[4],
                                        uint32_t b0, uint32_t b1) {
    asm volatile(
        "mma.sync.aligned.m16n8k16.row.col.f32.f16.f16.f32 "
        "{%0,%1,%2,%3}, {%4,%5,%6,%7}, {%8,%9}, {%0,%1,%2,%3};"
        : "+f"(d[0]), "+f"(d[1]), "+f"(d[2]), "+f"(d[3])
        : "r"(a[0]), "r"(a[1]), "r"(a[2]), "r"(a[3]), "r"(b0), "r"(b1));
}

// ---------------- prep: xs = fp16(x*w3), yt = fp16(y), bias dots in fp32 ----------------
__global__ void __launch_bounds__(256) prep_kernel(
    const float* __restrict__ x, const float* __restrict__ y, const float* __restrict__ WS) {
    int warp = blockIdx.x * 8 + (threadIdx.x >> 5);
    int lane = threadIdx.x & 31;
    const int nrows = BATCH * T;
    if (warp < nrows) {
        const float4* p4 = (const float4*)(x + (size_t)warp * D);
        const float4* w1 = (const float4*)WS;
        const float4* w3 = (const float4*)(WS + 2 * D);
        __half2* xs2 = (__half2*)(g_xs + (size_t)warp * D);
        float s = 0.f;
#pragma unroll
        for (int i = 0; i < 2; i++) {
            int idx = lane + i * 32;
            float4 v = p4[idx], a = w1[idx], c = w3[idx];
            s += v.x * a.x + v.y * a.y + v.z * a.z + v.w * a.w;
            xs2[idx * 2 + 0] = __floats2half2_rn(v.x * c.x, v.y * c.y);
            xs2[idx * 2 + 1] = __floats2half2_rn(v.z * c.z, v.w * c.w);
        }
#pragma unroll
        for (int o = 16; o; o >>= 1) s += __shfl_xor_sync(0xffffffffu, s, o);
        if (lane == 0) g_bias_x[warp] = s;
    } else {
        int row = warp - nrows;
        const float4* p4 = (const float4*)(y + (size_t)row * D);
        const float4* w2 = (const float4*)(WS + D);
        __half2* yt2 = (__half2*)(g_yt + (size_t)row * D);
        float s = 0.f;
#pragma unroll
        for (int i = 0; i < 2; i++) {
            int idx = lane + i * 32;
            float4 v = p4[idx], a = w2[idx];
            s += v.x * a.x + v.y * a.y + v.z * a.z + v.w * a.w;
            yt2[idx * 2 + 0] = __floats2half2_rn(v.x, v.y);
            yt2[idx * 2 + 1] = __floats2half2_rn(v.z, v.w);
        }
#pragma unroll
        for (int o = 16; o; o >>= 1) s += __shfl_xor_sync(0xffffffffu, s, o);
        if (lane == 0) g_bias_y[row] = s;
    }
}

// ---------------- fp16 warp-MMA GEMM: CTA 128x128, 128 threads, 4 warps of 64x64 ----------------
#define A_BYTES (BM * ROWB)            // 18432
#define B_BYTES (BN * ROWB)            // 18432
#define SMEM_BYTES (2 * A_BYTES + 2 * B_BYTES)   // 73728 -> 3 CTAs/SM

__global__ void __launch_bounds__(128, 3) gemm_mma_kernel(float* __restrict__ out) {
    extern __shared__ char smc[];
    const uint32_t sbase = smem_u32(smc);

    const int tid = threadIdx.x;
    const int wid = tid >> 5, lane = tid & 31;
    const int b = blockIdx.z;
    const int tile_m = blockIdx.y * BM;
    const int tile_n = blockIdx.x * BN;

    const __half* A  = g_xs + ((size_t)b * T + tile_m) * D;
    const __half* Bg = g_yt + ((size_t)b * T + tile_n) * D;

    // Warp layout: 2 (m) x 2 (n); warp tile 64 x 64
    const int warp_m = (wid >> 1) * 64;
    const int warp_n = (wid & 1) * 64;
    const int gid = lane >> 2;     // 0..7
    const int ctg = lane & 3;      // 0..3

    float acc[4][8][4];
#pragma unroll
    for (int i = 0; i < 4; i++)
#pragma unroll
        for (int j = 0; j < 8; j++)
#pragma unroll
            for (int r = 0; r < 4; r++) acc[i][j][r] = 0.f;

    // ldmatrix per-lane base addresses
    // A x4: m0=rows0-7/k0, m1=rows8-15/k0, m2=rows0-7/k8, m3=rows8-15/k8
    const uint32_t a_base = sbase
        + (uint32_t)(warp_m + (lane & 15)) * ROWB + (uint32_t)((lane >> 4) * 8) * 2;
    // B x4 per nf-pair: m0=(n0..7,k0), m1=(n0..7,k8), m2=(n8..15,k0), m3=(n8..15,k8)
    const uint32_t b_base = sbase + 2 * A_BYTES
        + (uint32_t)(warp_n + (lane & 7) + ((lane >> 4) & 1) * 8) * ROWB
        + (uint32_t)(((lane >> 3) & 1) * 8) * 2;

    // cp.async staging: per chunk per operand 128 rows x 8 16B-slots; 8 tasks/thread each
    const int st_row = tid >> 3;   // 0..15
    const int st_q   = tid & 7;    // 16B slot (8 halfs)

    auto load_chunk = [&](int chunk, int buf) {
        const __half* ap = A  + chunk * BK + st_q * 8;
        const __half* bp = Bg + chunk * BK + st_q * 8;
        uint32_t adst = sbase + buf * A_BYTES + st_row * ROWB + st_q * 16;
        uint32_t bdst = sbase + 2 * A_BYTES + buf * B_BYTES + st_row * ROWB + st_q * 16;
#pragma unroll
        for (int i = 0; i < 8; i++)
            cp_async16(adst + i * 16 * ROWB, ap + (size_t)(st_row + 16 * i) * D);
#pragma unroll
        for (int i = 0; i < 8; i++)
            cp_async16(bdst + i * 16 * ROWB, bp + (size_t)(st_row + 16 * i) * D);
    };

    load_chunk(0, 0);
    CP_COMMIT();
    CP_WAIT0();
    __syncthreads();

#pragma unroll 1
    for (int c = 0; c < NCH; c++) {
        if (c + 1 < NCH) {
            load_chunk(c + 1, (c + 1) & 1);
            CP_COMMIT();
        }

        const uint32_t abase = a_base + (c & 1) * A_BYTES;
        const uint32_t bbase = b_base + (c & 1) * B_BYTES;
#pragma unroll
        for (int ks = 0; ks < 4; ks++) {          // 4 k16 steps per 64-chunk
            const uint32_t koff = ks * 32;        // 16 halfs = 32 B
            uint32_t af[4][4], bq[4][4];
#pragma unroll
            for (int mf = 0; mf < 4; mf++)
                ldsm_x4(af[mf], abase + mf * 16 * ROWB + koff);
#pragma unroll
            for (int p = 0; p < 4; p++)
                ldsm_x4(bq[p], bbase + p * 16 * ROWB + koff);
#pragma unroll
            for (int mf = 0; mf < 4; mf++)
#pragma unroll
                for (int nf = 0; nf < 8; nf++)
                    mma_f16(acc[mf][nf], af[mf],
                            bq[nf >> 1][(nf & 1) * 2], bq[nf >> 1][(nf & 1) * 2 + 1]);
        }

        if (c + 1 < NCH) {
            CP_WAIT0();
            __syncthreads();
        }
    }

    // Epilogue: + bias_x[row] + bias_y[col], float2 stores
    const float* bxp = g_bias_x + b * T + tile_m + warp_m;
    const float* byp = g_bias_y + b * T + tile_n + warp_n;
    float2 by[8];
#pragma unroll
    for (int nf = 0; nf < 8; nf++)
        by[nf] = *(const float2*)(byp + nf * 8 + ctg * 2);

#pragma unroll
    for (int mf = 0; mf < 4; mf++) {
        int r0 = warp_m + mf * 16 + gid;
        float bx0 = bxp[mf * 16 + gid];
        float bx1 = bxp[mf * 16 + gid + 8];
        float* C0 = out + ((size_t)b * T + tile_m + r0) * T + tile_n + warp_n;
        float* C1 = C0 + 8 * T;
#pragma unroll
        for (int nf = 0; nf < 8; nf++) {
            int coff = nf * 8 + ctg * 2;
            float2 v0 = make_float2(acc[mf][nf][0] + bx0 + by[nf].x,
                                    acc[mf][nf][1] + bx0 + by[nf].y);
            float2 v1 = make_float2(acc[mf][nf][2] + bx1 + by[nf].x,
                                    acc[mf][nf][3] + bx1 + by[nf].y);
            *(float2*)(C0 + coff) = v0;
            *(float2*)(C1 + coff) = v1;
        }
    }
}

extern "C" void kernel_launch(void* const* d_in, const int* in_sizes, int n_in,
                              void* d_out, int out_size) {
    const float* x  = (const float*)d_in[0];
    const float* y  = (const float*)d_in[1];
    const float* WS = (const float*)d_in[2];
    float* out = (float*)d_out;

    cudaFuncSetAttribute(gemm_mma_kernel, cudaFuncAttributeMaxDynamicSharedMemorySize, SMEM_BYTES);

    prep_kernel<<<(2 * BATCH * T) / 8, 256>>>(x, y, WS);

    dim3 grid(T / BN, T / BM, BATCH);   // (8, 8, 16) = 1024 CTAs
    gemm_mma_kernel<<<grid, 128, SMEM_BYTES>>>(out);
}